// round 11
// baseline (speedup 1.0000x reference)
#include <cuda_runtime.h>
#include <cstdint>
#include <cfloat>
#include <math.h>

#define NX 12288
#define NYTOT 12288
#define DD 256
#define KSEL 30
#define SPLITS 3
#define NYS (NYTOT / SPLITS)      // 4096
#define BM 128
#define BN 128
#define BKC 16
#define NST (DD / BKC)            // 16 k-stages
#define CSTR 132                  // Cs row stride (floats), 16B-aligned rows
#define STGF (BKC * BM)           // 2048 floats per matrix slab
#define BUFF (2 * STGF)           // 4096 floats per ring stage (A+B)

// scratch (no allocations allowed)
__device__ __align__(16) float g_Xn[NX * DD];
__device__ __align__(16) float g_Yn[NYTOT * DD];
__device__ __align__(16) float g_XnT[DD * NX];     // k-major transposed
__device__ __align__(16) float g_YnT[DD * NYTOT];
__device__ float g_pv[NX * SPLITS * 2 * KSEL];
__device__ int   g_pi[NX * SPLITS * 2 * KSEL];

__device__ __forceinline__ void cpa16(unsigned int dst, const float* src) {
    asm volatile("cp.async.cg.shared.global [%0], [%1], 16;" :: "r"(dst), "l"(src));
}
__device__ __forceinline__ void cp_commit() {
    asm volatile("cp.async.commit_group;");
}
template <int N>
__device__ __forceinline__ void cp_wait() {
    asm volatile("cp.async.wait_group %0;" :: "n"(N));
}

// Issue one ring stage: 4 cp.async (2 A-rows, 2 B-rows) + commit.
__device__ __forceinline__ void issue_stage(unsigned int smb, int s, int ck0, int cf,
                                            const float* Asrc, const float* Bsrc) {
    unsigned int bufb = smb + (unsigned int)((s & 3) * BUFF) * 4u;
    int kb = s * BKC;
    cpa16(bufb + (unsigned int)((ck0 * BM + cf) * 4),              Asrc + (size_t)(kb + ck0) * NX);
    cpa16(bufb + (unsigned int)(((ck0 + 8) * BM + cf) * 4),        Asrc + (size_t)(kb + ck0 + 8) * NX);
    cpa16(bufb + (unsigned int)((STGF + ck0 * BN + cf) * 4),       Bsrc + (size_t)(kb + ck0) * NYTOT);
    cpa16(bufb + (unsigned int)((STGF + (ck0 + 8) * BN + cf) * 4), Bsrc + (size_t)(kb + ck0 + 8) * NYTOT);
    cp_commit();
}

// ---------------------------------------------------------------------------
// Row-normalize (validated R8-B numerics — DO NOT CHANGE):
// 128-thread row, vec2 partial add(mul,mul); warp xor tree 16..1; 4 warp sums
// -> shared; warp0 (lane<4 else 0) xor tree; m = max(sqrt_rn, 1e-8);
// inv = div_rn(1, m); out = x * inv.
// ---------------------------------------------------------------------------
__global__ __launch_bounds__(128)
void norm_kernel(const float* __restrict__ X, const float* __restrict__ Y) {
    __shared__ float sw[4];
    __shared__ float smv;
    int row = blockIdx.x;
    const float* src;
    float* dst;
    if (row < NX) { src = X + (size_t)row * DD; dst = g_Xn + (size_t)row * DD; }
    else { int r = row - NX; src = Y + (size_t)r * DD; dst = g_Yn + (size_t)r * DD; }

    int t = threadIdx.x;
    int lane = t & 31;
    int warp = t >> 5;

    float2 e = *(const float2*)(src + 2 * t);
    float p = __fadd_rn(__fmul_rn(e.x, e.x), __fmul_rn(e.y, e.y));
    #pragma unroll
    for (int o = 16; o > 0; o >>= 1)
        p = __fadd_rn(p, __shfl_xor_sync(0xffffffffu, p, o));
    if (lane == 0) sw[warp] = p;
    __syncthreads();
    if (warp == 0) {
        float v = (lane < 4) ? sw[lane] : 0.0f;
        #pragma unroll
        for (int o = 16; o > 0; o >>= 1)
            v = __fadd_rn(v, __shfl_xor_sync(0xffffffffu, v, o));
        if (lane == 0)
            smv = fmaxf(__fsqrt_rn(v), 1e-8f);
    }
    __syncthreads();
    float inv = __fdiv_rn(1.0f, smv);
    float2 o;
    o.x = __fmul_rn(e.x, inv);
    o.y = __fmul_rn(e.y, inv);
    *(float2*)(dst + 2 * t) = o;
}

// ---------------------------------------------------------------------------
// Tiled transpose: g_Xn[N][256] -> g_XnT[256][N] (and Y). Coalesced both sides.
// grid (N/32, 256/32, 2), block (32, 8).
// ---------------------------------------------------------------------------
__global__ void transpose_kernel() {
    __shared__ float tile[32][33];
    const float* src = blockIdx.z ? g_Yn : g_Xn;
    float* dst = blockIdx.z ? g_YnT : g_XnT;
    int n0 = blockIdx.x * 32;
    int k0 = blockIdx.y * 32;
    int tx = threadIdx.x, ty = threadIdx.y;
    #pragma unroll
    for (int i = ty; i < 32; i += 8)
        tile[i][tx] = src[(size_t)(n0 + i) * DD + k0 + tx];
    __syncthreads();
    #pragma unroll
    for (int i = ty; i < 32; i += 8)
        dst[(size_t)(k0 + i) * NX + n0 + tx] = tile[tx][i];
}

// ---------------------------------------------------------------------------
// Fused SGEMM (128x128 tile, BK=16) + running per-row top-30.
// cp.async 4-stage ring from k-major globals; conflict-free LDS.128 fragments;
// single ascending-k FMA chain per element (bitwise stable vs R8/R9).
// ---------------------------------------------------------------------------
__global__ __launch_bounds__(256, 2)
void simtopk_kernel() {
    extern __shared__ float sm[];
    float* Cs = sm;                         // [BM][CSTR], aliases ring (sync-separated)
    const unsigned int smb = (unsigned int)__cvta_generic_to_shared(sm);

    const int t = threadIdx.x;
    const int mbase = blockIdx.x * BM;
    const int sp = blockIdx.y;
    const int tx = t & 15;
    const int ty = t >> 4;
    const int lr = t & 127;
    const int lh = t >> 7;

    const int r0 = ty * 4, r1 = 64 + ty * 4;
    const int c0 = tx * 4, c1 = 64 + tx * 4;

    const int ck0 = t >> 5;                 // k-row within slab (0..7; +8 second)
    const int cf  = (t & 31) * 4;           // float offset within 128-wide row

    const float* Asrc = g_XnT + mbase + cf;

    float kv[KSEL];
    int   ki[KSEL];
    #pragma unroll
    for (int j = 0; j < KSEL; j++) { kv[j] = -FLT_MAX; ki[j] = 0x7fffffff; }
    float kth = -FLT_MAX;

    #pragma unroll 1
    for (int nt = 0; nt < NYS / BN; nt++) {
        const int nbase = sp * NYS + nt * BN;
        const float* Bsrc = g_YnT + nbase + cf;

        float acc[8][8];
        #pragma unroll
        for (int i = 0; i < 8; i++)
            #pragma unroll
            for (int j = 0; j < 8; j++) acc[i][j] = 0.0f;

        // prologue: stages 0..2
        issue_stage(smb, 0, ck0, cf, Asrc, Bsrc);
        issue_stage(smb, 1, ck0, cf, Asrc, Bsrc);
        issue_stage(smb, 2, ck0, cf, Asrc, Bsrc);

        #pragma unroll 1
        for (int ksg = 0; ksg < NST; ksg++) {
            if (ksg <= 13)      cp_wait<2>();
            else if (ksg == 14) cp_wait<1>();
            else                cp_wait<0>();
            __syncthreads();
            if (ksg < 13)
                issue_stage(smb, ksg + 3, ck0, cf, Asrc, Bsrc);

            const float* Ac = sm + (ksg & 3) * BUFF;
            const float* Bc = Ac + STGF;
            #pragma unroll
            for (int kk = 0; kk < BKC; kk++) {
                float a[8], b[8];
                *(float4*)(a)     = *(const float4*)(Ac + kk * BM + r0);
                *(float4*)(a + 4) = *(const float4*)(Ac + kk * BM + r1);
                *(float4*)(b)     = *(const float4*)(Bc + kk * BN + c0);
                *(float4*)(b + 4) = *(const float4*)(Bc + kk * BN + c1);
                #pragma unroll
                for (int i = 0; i < 8; i++)
                    #pragma unroll
                    for (int j = 0; j < 8; j++)
                        acc[i][j] = __fmaf_rn(a[i], b[j], acc[i][j]);
            }
        }
        __syncthreads();   // all warps done with ring before Cs overwrite

        // stage C tile to smem
        #pragma unroll
        for (int i = 0; i < 8; i++) {
            int row = (i < 4) ? (r0 + i) : (r1 + i - 4);
            #pragma unroll
            for (int j = 0; j < 8; j++) {
                int col = (j < 4) ? (c0 + j) : (c1 + j - 4);
                Cs[row * CSTR + col] = acc[i][j];
            }
        }
        __syncthreads();

        // running top-k: thread scans 64 candidates of its row, float4 loads
        {
            const float4* crow4 = (const float4*)(Cs + lr * CSTR + lh * 64);
            const int gbase = nbase + lh * 64;
            #pragma unroll 1
            for (int j4 = 0; j4 < 16; j4++) {
                float4 v4 = crow4[j4];
                #pragma unroll
                for (int q = 0; q < 4; q++) {
                    float v = (q == 0) ? v4.x : (q == 1) ? v4.y : (q == 2) ? v4.z : v4.w;
                    if (v > kth) {
                        int p = KSEL - 1;
                        while (p > 0 && kv[p - 1] < v) {
                            kv[p] = kv[p - 1];
                            ki[p] = ki[p - 1];
                            p--;
                        }
                        kv[p] = v;
                        ki[p] = gbase + j4 * 4 + q;
                        kth = kv[KSEL - 1];
                    }
                }
            }
        }
        __syncthreads();   // before next tile's prologue overwrites ring/Cs
    }

    // emit partial sorted list
    {
        const int row = mbase + lr;
        const size_t base = ((size_t)(row * SPLITS + sp) * 2 + lh) * KSEL;
        #pragma unroll 1
        for (int j = 0; j < KSEL; j++) {
            g_pv[base + j] = kv[j];
            g_pi[base + j] = ki[j];
        }
    }
}

// ---------------------------------------------------------------------------
// Merge 6 sorted partial lists per row -> final top-30; write values,u,v.
// Tie-break identical to jax.lax.top_k: value desc, index asc (stable).
// ---------------------------------------------------------------------------
__global__ void merge_kernel(float* __restrict__ out) {
    int r = blockIdx.x * blockDim.x + threadIdx.x;
    if (r >= NX) return;
    float mv[KSEL];
    int   mi[KSEL];
    #pragma unroll
    for (int j = 0; j < KSEL; j++) { mv[j] = -FLT_MAX; mi[j] = 0x7fffffff; }

    for (int l = 0; l < SPLITS * 2; l++) {
        const size_t base = ((size_t)r * SPLITS * 2 + l) * KSEL;
        for (int e = 0; e < KSEL; e++) {
            float v = g_pv[base + e];
            int idx = g_pi[base + e];
            float lv = mv[KSEL - 1];
            int   li = mi[KSEL - 1];
            bool better = (v > lv) || (v == lv && idx < li);
            if (!better) break;   // sorted list: rest can't qualify
            int p = KSEL - 1;
            while (p > 0 && (v > mv[p - 1] || (v == mv[p - 1] && idx < mi[p - 1]))) {
                mv[p] = mv[p - 1];
                mi[p] = mi[p - 1];
                p--;
            }
            mv[p] = v;
            mi[p] = idx;
        }
    }

    const size_t NK = (size_t)NX * KSEL;
    #pragma unroll 1
    for (int j = 0; j < KSEL; j++) {
        out[(size_t)r * KSEL + j]          = mv[j];        // values
        out[NK + (size_t)r * KSEL + j]     = (float)r;     // u
        out[2 * NK + (size_t)r * KSEL + j] = (float)mi[j]; // v
    }
}

extern "C" void kernel_launch(void* const* d_in, const int* in_sizes, int n_in,
                              void* d_out, int out_size) {
    const float* X = (const float*)d_in[0];
    const float* Y = (const float*)d_in[1];
    float* out = (float*)d_out;

    const int smem_bytes = BM * CSTR * 4;   // 67584 >= ring 65536
    cudaFuncSetAttribute(simtopk_kernel,
                         cudaFuncAttributeMaxDynamicSharedMemorySize, smem_bytes);

    norm_kernel<<<NX + NYTOT, 128>>>(X, Y);

    dim3 tgrid(NX / 32, DD / 32, 2);
    transpose_kernel<<<tgrid, dim3(32, 8)>>>();

    dim3 grid(NX / BM, SPLITS);
    simtopk_kernel<<<grid, 256, smem_bytes>>>();

    merge_kernel<<<(NX + 255) / 256, 256>>>(out);
}

// round 12
// speedup vs baseline: 1.0009x; 1.0009x over previous
#include <cuda_runtime.h>
#include <cstdint>
#include <cfloat>
#include <math.h>

#define NX 12288
#define NYTOT 12288
#define DD 256
#define KSEL 30
#define SPLITS 3
#define NYS (NYTOT / SPLITS)      // 4096
#define BM 128
#define BN 128
#define BKC 16
#define NST (DD / BKC)            // 16 k-stages
#define CSTR 132                  // Cs row stride (floats)
#define STGF (BKC * BM)           // 2048 floats per matrix slab
#define BUFF (2 * STGF)           // 4096 floats per ring stage (A+B)

// scratch (no allocations allowed)
__device__ __align__(16) float g_Xn[NX * DD];
__device__ __align__(16) float g_Yn[NYTOT * DD];
__device__ __align__(16) float g_XnT[DD * NX];     // k-major transposed
__device__ __align__(16) float g_YnT[DD * NYTOT];
__device__ float g_pv[SPLITS * 2 * KSEL * NX];     // [l][e][row] coalesced for merge
__device__ int   g_pi[SPLITS * 2 * KSEL * NX];

__device__ __forceinline__ void cpa16(unsigned int dst, const float* src) {
    asm volatile("cp.async.cg.shared.global [%0], [%1], 16;" :: "r"(dst), "l"(src));
}
__device__ __forceinline__ void cp_commit() {
    asm volatile("cp.async.commit_group;");
}
template <int N>
__device__ __forceinline__ void cp_wait() {
    asm volatile("cp.async.wait_group %0;" :: "n"(N));
}

// Issue one ring stage: 4 cp.async (2 A-rows, 2 B-rows) + commit.
__device__ __forceinline__ void issue_stage(unsigned int smb, int s, int ck0, int cf,
                                            const float* Asrc, const float* Bsrc) {
    unsigned int bufb = smb + (unsigned int)((s & 3) * BUFF) * 4u;
    int kb = s * BKC;
    cpa16(bufb + (unsigned int)((ck0 * BM + cf) * 4),              Asrc + (size_t)(kb + ck0) * NX);
    cpa16(bufb + (unsigned int)(((ck0 + 8) * BM + cf) * 4),        Asrc + (size_t)(kb + ck0 + 8) * NX);
    cpa16(bufb + (unsigned int)((STGF + ck0 * BN + cf) * 4),       Bsrc + (size_t)(kb + ck0) * NYTOT);
    cpa16(bufb + (unsigned int)((STGF + (ck0 + 8) * BN + cf) * 4), Bsrc + (size_t)(kb + ck0 + 8) * NYTOT);
    cp_commit();
}

// ---------------------------------------------------------------------------
// Row-normalize (validated R8-B numerics — DO NOT CHANGE).
// ---------------------------------------------------------------------------
__global__ __launch_bounds__(128)
void norm_kernel(const float* __restrict__ X, const float* __restrict__ Y) {
    __shared__ float sw[4];
    __shared__ float smv;
    int row = blockIdx.x;
    const float* src;
    float* dst;
    if (row < NX) { src = X + (size_t)row * DD; dst = g_Xn + (size_t)row * DD; }
    else { int r = row - NX; src = Y + (size_t)r * DD; dst = g_Yn + (size_t)r * DD; }

    int t = threadIdx.x;
    int lane = t & 31;
    int warp = t >> 5;

    float2 e = *(const float2*)(src + 2 * t);
    float p = __fadd_rn(__fmul_rn(e.x, e.x), __fmul_rn(e.y, e.y));
    #pragma unroll
    for (int o = 16; o > 0; o >>= 1)
        p = __fadd_rn(p, __shfl_xor_sync(0xffffffffu, p, o));
    if (lane == 0) sw[warp] = p;
    __syncthreads();
    if (warp == 0) {
        float v = (lane < 4) ? sw[lane] : 0.0f;
        #pragma unroll
        for (int o = 16; o > 0; o >>= 1)
            v = __fadd_rn(v, __shfl_xor_sync(0xffffffffu, v, o));
        if (lane == 0)
            smv = fmaxf(__fsqrt_rn(v), 1e-8f);
    }
    __syncthreads();
    float inv = __fdiv_rn(1.0f, smv);
    float2 o;
    o.x = __fmul_rn(e.x, inv);
    o.y = __fmul_rn(e.y, inv);
    *(float2*)(dst + 2 * t) = o;
}

// ---------------------------------------------------------------------------
// Tiled transpose: g_Xn[N][256] -> g_XnT[256][N] (and Y).
// ---------------------------------------------------------------------------
__global__ void transpose_kernel() {
    __shared__ float tile[32][33];
    const float* src = blockIdx.z ? g_Yn : g_Xn;
    float* dst = blockIdx.z ? g_YnT : g_XnT;
    int n0 = blockIdx.x * 32;
    int k0 = blockIdx.y * 32;
    int tx = threadIdx.x, ty = threadIdx.y;
    #pragma unroll
    for (int i = ty; i < 32; i += 8)
        tile[i][tx] = src[(size_t)(n0 + i) * DD + k0 + tx];
    __syncthreads();
    #pragma unroll
    for (int i = ty; i < 32; i += 8)
        dst[(size_t)(k0 + i) * NX + n0 + tx] = tile[tx][i];
}

// ---------------------------------------------------------------------------
// Fused SGEMM (128x128, BK=16) + running top-30.
// Occupancy 1 (255 regs), cp.async 4-stage ring, register-double-buffered
// fragments. Single ascending-k FMA chain per element (bitwise stable).
// ---------------------------------------------------------------------------
__global__ __launch_bounds__(256, 1)
void simtopk_kernel() {
    extern __shared__ float sm[];
    float* Cs = sm;                         // aliases ring (sync-separated)
    const unsigned int smb = (unsigned int)__cvta_generic_to_shared(sm);

    const int t = threadIdx.x;
    const int mbase = blockIdx.x * BM;
    const int sp = blockIdx.y;
    const int tx = t & 15;
    const int ty = t >> 4;
    const int lr = t & 127;
    const int lh = t >> 7;

    const int r0 = ty * 4, r1 = 64 + ty * 4;
    const int c0 = tx * 4, c1 = 64 + tx * 4;

    const int ck0 = t >> 5;                 // k-row within slab (0..7; +8 second)
    const int cf  = (t & 31) * 4;           // float offset within 128-wide row

    const float* Asrc = g_XnT + mbase + cf;

    float kv[KSEL];
    int   ki[KSEL];
    #pragma unroll
    for (int j = 0; j < KSEL; j++) { kv[j] = -FLT_MAX; ki[j] = 0x7fffffff; }
    float kth = -FLT_MAX;

    #pragma unroll 1
    for (int nt = 0; nt < NYS / BN; nt++) {
        const int nbase = sp * NYS + nt * BN;
        const float* Bsrc = g_YnT + nbase + cf;

        float acc[8][8];
        #pragma unroll
        for (int i = 0; i < 8; i++)
            #pragma unroll
            for (int j = 0; j < 8; j++) acc[i][j] = 0.0f;

        issue_stage(smb, 0, ck0, cf, Asrc, Bsrc);
        issue_stage(smb, 1, ck0, cf, Asrc, Bsrc);
        issue_stage(smb, 2, ck0, cf, Asrc, Bsrc);

        #pragma unroll 1
        for (int ksg = 0; ksg < NST; ksg++) {
            if (ksg <= 13)      cp_wait<2>();
            else if (ksg == 14) cp_wait<1>();
            else                cp_wait<0>();
            __syncthreads();
            if (ksg < 13)
                issue_stage(smb, ksg + 3, ck0, cf, Asrc, Bsrc);

            const float* Ac = sm + (ksg & 3) * BUFF;
            const float* Bc = Ac + STGF;

            // register double-buffered fragments
            float a[2][8], b[2][8];
            *(float4*)(a[0])     = *(const float4*)(Ac + r0);
            *(float4*)(a[0] + 4) = *(const float4*)(Ac + r1);
            *(float4*)(b[0])     = *(const float4*)(Bc + c0);
            *(float4*)(b[0] + 4) = *(const float4*)(Bc + c1);
            #pragma unroll
            for (int kk = 0; kk < BKC; kk++) {
                const int cur = kk & 1;
                if (kk < BKC - 1) {
                    const int nxt = cur ^ 1;
                    *(float4*)(a[nxt])     = *(const float4*)(Ac + (kk + 1) * BM + r0);
                    *(float4*)(a[nxt] + 4) = *(const float4*)(Ac + (kk + 1) * BM + r1);
                    *(float4*)(b[nxt])     = *(const float4*)(Bc + (kk + 1) * BN + c0);
                    *(float4*)(b[nxt] + 4) = *(const float4*)(Bc + (kk + 1) * BN + c1);
                }
                #pragma unroll
                for (int i = 0; i < 8; i++)
                    #pragma unroll
                    for (int j = 0; j < 8; j++)
                        acc[i][j] = __fmaf_rn(a[cur][i], b[cur][j], acc[i][j]);
            }
        }
        __syncthreads();   // ring use done before Cs overwrite

        // stage C tile to smem
        #pragma unroll
        for (int i = 0; i < 8; i++) {
            int row = (i < 4) ? (r0 + i) : (r1 + i - 4);
            #pragma unroll
            for (int j = 0; j < 8; j++) {
                int col = (j < 4) ? (c0 + j) : (c1 + j - 4);
                Cs[row * CSTR + col] = acc[i][j];
            }
        }
        __syncthreads();

        // running top-k: thread scans 64 candidates of its row
        {
            const float4* crow4 = (const float4*)(Cs + lr * CSTR + lh * 64);
            const int gbase = nbase + lh * 64;
            #pragma unroll 1
            for (int j4 = 0; j4 < 16; j4++) {
                float4 v4 = crow4[j4];
                #pragma unroll
                for (int q = 0; q < 4; q++) {
                    float v = (q == 0) ? v4.x : (q == 1) ? v4.y : (q == 2) ? v4.z : v4.w;
                    if (v > kth) {
                        int p = KSEL - 1;
                        while (p > 0 && kv[p - 1] < v) {
                            kv[p] = kv[p - 1];
                            ki[p] = ki[p - 1];
                            p--;
                        }
                        kv[p] = v;
                        ki[p] = gbase + j4 * 4 + q;
                        kth = kv[KSEL - 1];
                    }
                }
            }
        }
        __syncthreads();   // before next tile's prologue overwrites ring/Cs
    }

    // emit partial sorted list (coalesced-for-merge layout: [l][e][row])
    {
        const int row = mbase + lr;
        const int l = sp * 2 + lh;
        #pragma unroll 1
        for (int j = 0; j < KSEL; j++) {
            g_pv[(size_t)(l * KSEL + j) * NX + row] = kv[j];
            g_pi[(size_t)(l * KSEL + j) * NX + row] = ki[j];
        }
    }
}

// ---------------------------------------------------------------------------
// Merge 6 sorted partial lists per row -> final top-30; write values,u,v.
// Tie-break identical to jax.lax.top_k (value desc, index asc). Coalesced reads.
// ---------------------------------------------------------------------------
__global__ void merge_kernel(float* __restrict__ out) {
    int r = blockIdx.x * blockDim.x + threadIdx.x;
    if (r >= NX) return;
    float mv[KSEL];
    int   mi[KSEL];
    #pragma unroll
    for (int j = 0; j < KSEL; j++) { mv[j] = -FLT_MAX; mi[j] = 0x7fffffff; }

    for (int l = 0; l < SPLITS * 2; l++) {
        for (int e = 0; e < KSEL; e++) {
            float v = g_pv[(size_t)(l * KSEL + e) * NX + r];
            int idx = g_pi[(size_t)(l * KSEL + e) * NX + r];
            float lv = mv[KSEL - 1];
            int   li = mi[KSEL - 1];
            bool better = (v > lv) || (v == lv && idx < li);
            if (!better) break;   // sorted list: rest can't qualify
            int p = KSEL - 1;
            while (p > 0 && (v > mv[p - 1] || (v == mv[p - 1] && idx < mi[p - 1]))) {
                mv[p] = mv[p - 1];
                mi[p] = mi[p - 1];
                p--;
            }
            mv[p] = v;
            mi[p] = idx;
        }
    }

    const size_t NK = (size_t)NX * KSEL;
    #pragma unroll 1
    for (int j = 0; j < KSEL; j++) {
        out[(size_t)r * KSEL + j]          = mv[j];        // values
        out[NK + (size_t)r * KSEL + j]     = (float)r;     // u
        out[2 * NK + (size_t)r * KSEL + j] = (float)mi[j]; // v
    }
}

extern "C" void kernel_launch(void* const* d_in, const int* in_sizes, int n_in,
                              void* d_out, int out_size) {
    const float* X = (const float*)d_in[0];
    const float* Y = (const float*)d_in[1];
    float* out = (float*)d_out;

    const int smem_bytes = BM * CSTR * 4;   // 67584 >= ring 65536
    cudaFuncSetAttribute(simtopk_kernel,
                         cudaFuncAttributeMaxDynamicSharedMemorySize, smem_bytes);

    norm_kernel<<<NX + NYTOT, 128>>>(X, Y);

    dim3 tgrid(NX / 32, DD / 32, 2);
    transpose_kernel<<<tgrid, dim3(32, 8)>>>();

    dim3 grid(NX / BM, SPLITS);
    simtopk_kernel<<<grid, 256, smem_bytes>>>();

    merge_kernel<<<(NX + 255) / 256, 256>>>(out);
}